// round 1
// baseline (speedup 1.0000x reference)
#include <cuda_runtime.h>
#include <cuda_bf16.h>
#include <math.h>

#define TAU 0.5f
#define B 16
#define H 96
#define W 96
#define NPIX (H*W)
#define NMASK 32          // 16 pred masks + 16 label masks
#define BIGD 1000         // sentinel row-distance (1000^2 >> max real d2 = 18050)

// scratch (static device globals; no allocation)
__device__ int g_g2[NMASK * NPIX];   // squared row-distance, then used by row pass
__device__ int g_any[NMASK];         // nonempty flags
__device__ int g_maxAB[B];           // max over pred-points of min d2 to label set
__device__ int g_maxBA[B];           // max over label-points of min d2 to pred set

// ---------------------------------------------------------------------------
// Kernel 1: threshold + column-wise distance pass.
// grid = 32 blocks (one per mask image), 96 threads (one per column).
// ---------------------------------------------------------------------------
__global__ void hd_colpass(const float* __restrict__ pred,
                           const float* __restrict__ tgt)
{
    const int b = blockIdx.x;      // mask index 0..31
    const int x = threadIdx.x;     // column 0..95
    const float* src = (b < B) ? (pred + b * NPIX) : (tgt + (b - B) * NPIX);
    int* g2 = g_g2 + b * NPIX;

    // zero the per-image accumulators once per launch
    if (b == 0 && x < B) { g_maxAB[x] = 0; g_maxBA[x] = 0; }

    int any = 0;
    int d = BIGD;
    #pragma unroll 4
    for (int y = 0; y < H; y++) {
        int m = (src[y * W + x] >= TAU);
        any |= m;
        d = m ? 0 : min(d + 1, BIGD);
        g2[y * W + x] = d;                 // forward distance (temp)
    }
    d = BIGD;
    #pragma unroll 4
    for (int y = H - 1; y >= 0; y--) {
        int m = (src[y * W + x] >= TAU);
        d = m ? 0 : min(d + 1, BIGD);
        int dd = min(d, g2[y * W + x]);
        g2[y * W + x] = dd * dd;           // squared min row-distance
    }

    __shared__ int s_any;
    if (x == 0) s_any = 0;
    __syncthreads();
    if (any) atomicOr(&s_any, 1);
    __syncthreads();
    if (x == 0) g_any[b] = s_any;
}

// ---------------------------------------------------------------------------
// Kernel 2: row-wise min-plus pass + per-image max reduction.
// grid = 16*96 blocks (image,row), 96 threads (one per output column).
// ---------------------------------------------------------------------------
__global__ void hd_rowpass(const float* __restrict__ pred,
                           const float* __restrict__ tgt)
{
    const int img = blockIdx.x / H;
    const int y   = blockIdx.x % H;
    const int x   = threadIdx.x;

    __shared__ int g2P[W];   // squared row-dist for pred mask, this row
    __shared__ int g2L[W];   // squared row-dist for label mask, this row
    __shared__ int redA[W];
    __shared__ int redB[W];

    g2P[x] = g_g2[img * NPIX + y * W + x];
    g2L[x] = g_g2[(B + img) * NPIX + y * W + x];
    const int pv = (pred[img * NPIX + y * W + x] >= TAU);
    const int lv = (tgt [img * NPIX + y * W + x] >= TAU);
    __syncthreads();

    int mAB = 0x7FFFFFFF;    // min over label set of d2 (for a pred point here)
    int mBA = 0x7FFFFFFF;    // min over pred set of d2 (for a label point here)
    #pragma unroll 8
    for (int j = 0; j < W; j++) {
        int dx = x - j;
        int dx2 = dx * dx;
        mAB = min(mAB, dx2 + g2L[j]);
        mBA = min(mBA, dx2 + g2P[j]);
    }

    redA[x] = pv ? mAB : -1;
    redB[x] = lv ? mBA : -1;
    __syncthreads();

    if (x < 32) {
        int a  = max(redA[x], max(redA[x + 32], redA[x + 64]));
        int bb = max(redB[x], max(redB[x + 32], redB[x + 64]));
        #pragma unroll
        for (int o = 16; o > 0; o >>= 1) {
            a  = max(a,  __shfl_xor_sync(0xFFFFFFFFu, a,  o));
            bb = max(bb, __shfl_xor_sync(0xFFFFFFFFu, bb, o));
        }
        if (x == 0) {
            atomicMax(&g_maxAB[img], a);
            atomicMax(&g_maxBA[img], bb);
        }
    }
}

// ---------------------------------------------------------------------------
// Kernel 3: finalize. One block. Empty-set fallback (diameter) included for
// formal correctness; with random-uniform inputs it never executes.
// ---------------------------------------------------------------------------
__global__ void hd_finalize(const float* __restrict__ pred,
                            const float* __restrict__ tgt,
                            float* __restrict__ out)
{
    const int tid = threadIdx.x;
    __shared__ float hd[B];
    __shared__ int needs[B];     // 0 = normal, 1 = diam(pred), 2 = diam(label)
    __shared__ int sred[256];

    if (tid < B) {
        int aa = g_any[tid];
        int bb = g_any[B + tid];
        if (aa && bb) {
            hd[tid] = sqrtf((float)max(g_maxAB[tid], g_maxBA[tid]));
            needs[tid] = 0;
        } else if (!aa && !bb) {
            hd[tid] = 0.0f;
            needs[tid] = 0;
        } else {
            needs[tid] = aa ? 1 : 2;
        }
    }
    __syncthreads();

    for (int img = 0; img < B; img++) {
        if (needs[img]) {   // uniform over the block (shared)
            const float* src = (needs[img] == 1) ? (pred + img * NPIX)
                                                 : (tgt  + img * NPIX);
            int best = 0;
            for (int p = tid; p < NPIX; p += blockDim.x) {
                if (src[p] >= TAU) {
                    int py = p / W, px = p % W;
                    for (int q = 0; q < NPIX; q++) {
                        if (src[q] >= TAU) {
                            int dy = py - q / W;
                            int dx = px - q % W;
                            best = max(best, dy * dy + dx * dx);
                        }
                    }
                }
            }
            sred[tid] = best;
            __syncthreads();
            for (int s = 128; s > 0; s >>= 1) {
                if (tid < s) sred[tid] = max(sred[tid], sred[tid + s]);
                __syncthreads();
            }
            if (tid == 0) hd[img] = sqrtf((float)sred[0]);
            __syncthreads();
        }
    }

    if (tid == 0) {
        float s = 0.0f;
        #pragma unroll
        for (int i = 0; i < B; i++) s += hd[i];
        out[0] = s * (1.0f / B);
    }
}

// ---------------------------------------------------------------------------
extern "C" void kernel_launch(void* const* d_in, const int* in_sizes, int n_in,
                              void* d_out, int out_size)
{
    const float* pred = (const float*)d_in[0];
    const float* tgt  = (const float*)d_in[1];
    float* out = (float*)d_out;

    hd_colpass<<<NMASK, W>>>(pred, tgt);
    hd_rowpass<<<B * H, W>>>(pred, tgt);
    hd_finalize<<<1, 256>>>(pred, tgt, out);
}

// round 3
// speedup vs baseline: 1.2718x; 1.2718x over previous
#include <cuda_runtime.h>
#include <cuda_bf16.h>
#include <cstdint>
#include <math.h>

#define TAU 0.5f
#define B 16
#define H 96
#define W 96
#define NPIX (H*W)
#define NMASK 32          // 16 pred masks + 16 label masks
#define DSENT 200         // sentinel row-distance; 200^2=40000 > max real d2=18050

// static device scratch (no allocation)
__device__ uint32_t g_colmask[NMASK * 3 * W];  // [mask][word(3)][x] column bitmasks
__device__ int g_anyw[NMASK * 3];              // per (word-row, mask) nonempty flag
__device__ int g_maxAB[B];
__device__ int g_maxBA[B];
__device__ int g_done = 0;

// ---------------------------------------------------------------------------
// Kernel A: threshold + column bit-pack.
// grid = 96 blocks = (word-row w in 0..2) x (mask 0..31), block = 96 threads (x).
// Each thread: 32 coalesced loads -> one u32 (bit r = mask at row w*32+r, col x).
// ---------------------------------------------------------------------------
__global__ void hd_buildmask(const float* __restrict__ pred,
                             const float* __restrict__ tgt)
{
    const int bi   = blockIdx.x;
    const int mask = bi % NMASK;
    const int w    = bi / NMASK;        // 0..2
    const int x    = threadIdx.x;
    const float* src = (mask < B) ? (pred + mask * NPIX)
                                  : (tgt + (mask - B) * NPIX);
    uint32_t word = 0;
    #pragma unroll
    for (int r = 0; r < 32; r++) {
        word |= (src[(w * 32 + r) * W + x] >= TAU ? 1u : 0u) << r;
    }
    g_colmask[mask * (3 * W) + w * W + x] = word;

    __shared__ int s_any;
    if (x == 0) s_any = 0;
    __syncthreads();
    if (word) atomicOr(&s_any, 1);
    __syncthreads();
    if (x == 0) g_anyw[bi] = s_any;

    if (bi == 0 && x < B) { g_maxAB[x] = 0; g_maxBA[x] = 0; }
}

// ---------------------------------------------------------------------------
// helpers: nearest-set-bit row distance squared, from 3-word column mask.
// kb* / ka* are precomputed "rows <= y" / "rows >= y" keep-masks (uniform per block).
// ---------------------------------------------------------------------------
__device__ __forceinline__ int col_g2(uint32_t m0, uint32_t m1, uint32_t m2, int y,
                                      uint32_t kb0, uint32_t kb1, uint32_t kb2,
                                      uint32_t ka0, uint32_t ka1, uint32_t ka2)
{
    int hi = -100000;
    uint32_t v;
    v = m0 & kb0; if (v) hi = 31 - __clz(v);
    v = m1 & kb1; if (v) hi = 63 - __clz(v);
    v = m2 & kb2; if (v) hi = 95 - __clz(v);
    int lo = 100000;
    v = m2 & ka2; if (v) lo = 64 + __ffs(v) - 1;
    v = m1 & ka1; if (v) lo = 32 + __ffs(v) - 1;
    v = m0 & ka0; if (v) lo = __ffs(v) - 1;
    int d = min(y - hi, lo - y);
    d = min(d, DSENT);
    return d * d;
}

__device__ __forceinline__ uint32_t below_keep(int y, int base) {
    int t = y - base;
    if (t < 0) return 0u;
    if (t >= 31) return 0xFFFFFFFFu;
    return 0xFFFFFFFFu >> (31 - t);
}
__device__ __forceinline__ uint32_t above_keep(int y, int base) {
    int t = y - base;
    if (t <= 0) return 0xFFFFFFFFu;
    if (t > 31) return 0u;
    return 0xFFFFFFFFu << t;
}

// ---------------------------------------------------------------------------
// Kernel B: per (image,row) min-plus + per-image max; last block finalizes.
// grid = B*H = 1536, block = 96.
// ---------------------------------------------------------------------------
__global__ void hd_main(const float* __restrict__ pred,
                        const float* __restrict__ tgt,
                        float* __restrict__ out)
{
    const int img = blockIdx.x / H;
    const int y   = blockIdx.x % H;
    const int x   = threadIdx.x;

    __shared__ uint32_t sP[3][W], sL[3][W];
    __shared__ int g2P[W], g2L[W], redA[W], redB[W];

    #pragma unroll
    for (int w = 0; w < 3; w++) {
        sP[w][x] = g_colmask[img * (3 * W) + w * W + x];
        sL[w][x] = g_colmask[(B + img) * (3 * W) + w * W + x];
    }
    __syncthreads();

    // uniform keep-masks for this row
    const uint32_t kb0 = below_keep(y, 0),  kb1 = below_keep(y, 32), kb2 = below_keep(y, 64);
    const uint32_t ka0 = above_keep(y, 0),  ka1 = above_keep(y, 32), ka2 = above_keep(y, 64);

    g2P[x] = col_g2(sP[0][x], sP[1][x], sP[2][x], y, kb0, kb1, kb2, ka0, ka1, ka2);
    g2L[x] = col_g2(sL[0][x], sL[1][x], sL[2][x], y, kb0, kb1, kb2, ka0, ka1, ka2);
    const int pv = (sP[y >> 5][x] >> (y & 31)) & 1;
    const int lv = (sL[y >> 5][x] >> (y & 31)) & 1;
    __syncthreads();

    int mAB = 0x7FFFFFFF;   // min over label set of d2 for pred point (y,x)
    int mBA = 0x7FFFFFFF;
    #pragma unroll 8
    for (int j = 0; j < W; j++) {
        int dx  = x - j;
        int dx2 = dx * dx;
        mAB = min(mAB, dx2 + g2L[j]);
        mBA = min(mBA, dx2 + g2P[j]);
    }

    redA[x] = pv ? mAB : -1;
    redB[x] = lv ? mBA : -1;
    __syncthreads();

    __shared__ int s_isLast;
    if (x < 32) {
        int a  = max(redA[x], max(redA[x + 32], redA[x + 64]));
        int bb = max(redB[x], max(redB[x + 32], redB[x + 64]));
        #pragma unroll
        for (int o = 16; o > 0; o >>= 1) {
            a  = max(a,  __shfl_xor_sync(0xFFFFFFFFu, a,  o));
            bb = max(bb, __shfl_xor_sync(0xFFFFFFFFu, bb, o));
        }
        if (x == 0) {
            atomicMax(&g_maxAB[img], a);
            atomicMax(&g_maxBA[img], bb);
            __threadfence();
            int old = atomicAdd(&g_done, 1);
            s_isLast = (old == B * H - 1);
        }
    }
    __syncthreads();
    if (!s_isLast) return;

    // ---------------- finalize (runs in exactly one block) ----------------
    __shared__ float hd[B];
    __shared__ int needs[B];   // 0 normal, 1 diam(pred), 2 diam(label)
    if (x < B) {
        int aa = g_anyw[x]      | g_anyw[32 + x]      | g_anyw[64 + x];
        int bb = g_anyw[B + x]  | g_anyw[32 + B + x]  | g_anyw[64 + B + x];
        if (aa && bb) {
            int dab = atomicMax(&g_maxAB[x], 0);   // atomic read (final value)
            int dba = atomicMax(&g_maxBA[x], 0);
            hd[x] = sqrtf((float)max(dab, dba));
            needs[x] = 0;
        } else if (!aa && !bb) {
            hd[x] = 0.0f;
            needs[x] = 0;
        } else {
            needs[x] = aa ? 1 : 2;
        }
    }
    __syncthreads();

    // empty-set fallback: diameter of the nonempty set (formal correctness;
    // never executes for random-uniform inputs).
    __shared__ int sred[W];
    for (int im = 0; im < B; im++) {
        if (needs[im]) {
            const float* src = (needs[im] == 1) ? (pred + im * NPIX)
                                                : (tgt  + im * NPIX);
            int best = 0;
            for (int p = x; p < NPIX; p += W) {
                if (src[p] >= TAU) {
                    int py = p / W, px = p % W;
                    for (int q = 0; q < NPIX; q++) {
                        if (src[q] >= TAU) {
                            int dy = py - q / W;
                            int dxx = px - q % W;
                            best = max(best, dy * dy + dxx * dxx);
                        }
                    }
                }
            }
            sred[x] = best;
            __syncthreads();
            if (x == 0) {
                int m = 0;
                for (int t = 0; t < W; t++) m = max(m, sred[t]);
                hd[im] = sqrtf((float)m);
            }
            __syncthreads();
        }
    }

    if (x == 0) {
        float s = 0.0f;
        #pragma unroll
        for (int i = 0; i < B; i++) s += hd[i];
        out[0] = s * (1.0f / B);
        g_done = 0;   // reset for next graph replay
    }
}

// ---------------------------------------------------------------------------
extern "C" void kernel_launch(void* const* d_in, const int* in_sizes, int n_in,
                              void* d_out, int out_size)
{
    const float* pred = (const float*)d_in[0];
    const float* tgt  = (const float*)d_in[1];
    float* out = (float*)d_out;

    hd_buildmask<<<NMASK * 3, W>>>(pred, tgt);
    hd_main<<<B * H, W>>>(pred, tgt, out);
}